// round 13
// baseline (speedup 1.0000x reference)
#include <cuda_runtime.h>

// LengthRegulator: B=32, T=1024, C=384, M=4096. Durations int32; totals appended
// to out as float32 values (confirmed R4/R5).
//
// R13: ONE kernel, role-split blocks + flag handshake.
//   blocks [0,256):    prep  — per-(batch,seg) scan + tok for 512 frames
//   blocks [256,16640): gather — R12 frame-blocked gather, spin on seg flag
// Flags self-clean (64th gather block per seg resets) -> replay-deterministic.

#define BB 32
#define TT 1024
#define CC 384
#define MM 4096
#define C4 (CC / 4)                              // 96 float4 per row
#define MAIN_ELEMS ((long long)BB * MM * CC)     // 50,331,648
#define SEG 8                                    // prep segments per batch
#define FSEG (MM / SEG)                          // 512 frames per segment
#define NPREP (BB * SEG)                         // 256 prep blocks
#define FPB 8                                    // frames per gather block
#define GPB (MM / FPB)                           // 512 gather blocks per batch
#define NGATH (BB * GPB)                         // 16384
#define GBLK (FSEG / FPB)                        // 64 gather blocks per segment

__device__ int g_tok[BB * MM];                   // tok per frame, -1 => zero
__device__ int g_flag[NPREP];                    // seg ready flags (zero-init)
__device__ int g_done[NPREP];                    // gather arrival tickets

__global__ __launch_bounds__(256) void lr_fused_kernel(
        const int4* __restrict__ dur4,           // durations as int4 quads
        const float4* __restrict__ x4,
        float4* __restrict__ out4,
        float* __restrict__ out_base) {
    __shared__ int cs[TT];
    __shared__ int wsum[8];
    __shared__ int stok[FPB];

    const int bid = blockIdx.x;
    const int tid = threadIdx.x;

    if (bid < NPREP) {
        // ------------------------- PREP ROLE -------------------------
        const int b   = bid >> 3;
        const int seg = bid & 7;
        const int lane = tid & 31;
        const int w    = tid >> 5;               // warp 0..7

        const int4 d = dur4[b * (TT / 4) + tid]; // 4 durations per thread
        int e = d.x + d.y + d.z + d.w;
        #pragma unroll
        for (int off = 1; off < 32; off <<= 1) {
            int n = __shfl_up_sync(0xffffffffu, e, off);
            if (lane >= off) e += n;
        }
        if (lane == 31) wsum[w] = e;
        __syncthreads();
        if (tid < 32) {
            int s = (tid < 8) ? wsum[tid] : 0;
            #pragma unroll
            for (int off = 1; off < 8; off <<= 1) {
                int n = __shfl_up_sync(0xffffffffu, s, off);
                if (lane >= off) s += n;
            }
            if (tid < 8) wsum[tid] = s;
        }
        __syncthreads();
        const int base = (w > 0) ? wsum[w - 1] : 0;
        const int end = base + e;                // inclusive through 4t+3
        cs[4 * tid + 3] = end;
        cs[4 * tid + 2] = end - d.w;
        cs[4 * tid + 1] = end - d.w - d.z;
        cs[4 * tid + 0] = end - d.w - d.z - d.y;
        __syncthreads();

        const int total = cs[TT - 1];
        if (seg == 0 && tid == 0)
            out_base[MAIN_ELEMS + b] = (float)total;  // total as float32

        #pragma unroll
        for (int k = 0; k < 2; ++k) {
            const int f = seg * FSEG + k * 256 + tid;
            int pos = 0;                          // upper_bound, bit construction
            #pragma unroll
            for (int step = TT / 2; step > 0; step >>= 1) {
                int cand = pos + step;            // cand-1 <= 1022
                if (cs[cand - 1] <= f) pos = cand;
            }
            g_tok[b * MM + f] = (f < total) ? pos : -1;
        }
        __threadfence();                          // publish g_tok
        __syncthreads();
        if (tid == 0)
            asm volatile("st.release.gpu.global.b32 [%0], %1;"
                         :: "l"(&g_flag[bid]), "r"(1) : "memory");
    } else {
        // ------------------------ GATHER ROLE ------------------------
        const int g   = bid - NPREP;
        const int b   = g >> 9;                   // / GPB
        const int rem = g & (GPB - 1);
        const int f0  = rem << 3;                 // * FPB
        const int fi  = b * SEG + (rem >> 6);     // flag index (seg = f0/FSEG)

        if (tid == 0) {
            int r;
            do {
                asm volatile("ld.acquire.gpu.global.b32 %0, [%1];"
                             : "=r"(r) : "l"(&g_flag[fi]) : "memory");
                if (!r) __nanosleep(64);
            } while (!r);
            // self-cleaning lifecycle: 64th arrival resets flag + ticket
            int c = atomicAdd(&g_done[fi], 1);
            if (c == GBLK - 1) { g_done[fi] = 0; __threadfence(); g_flag[fi] = 0; }
        }
        __syncthreads();

        if (tid < FPB)
            stok[tid] = __ldcg(&g_tok[b * MM + f0 + tid]);
        __syncthreads();

        const int obase = (b * MM + f0) * C4;     // < 12.6M, fits int
        const int xbase = b * TT * C4;

        float4 val[3];
        #pragma unroll
        for (int k = 0; k < 3; ++k) {
            const int e  = k * 256 + tid;         // 0..767
            const int fl = e / C4;                // local frame 0..7
            const int c  = e - fl * C4;
            const int tok = stok[fl];
            val[k] = make_float4(0.f, 0.f, 0.f, 0.f);
            if (tok >= 0)
                val[k] = __ldg(&x4[xbase + tok * C4 + c]);
        }
        #pragma unroll
        for (int k = 0; k < 3; ++k)
            __stcs(&out4[obase + k * 256 + tid], val[k]);
    }
}

// ---------------------------------------------------------------------------

extern "C" void kernel_launch(void* const* d_in, const int* in_sizes, int n_in,
                              void* d_out, int out_size) {
    const float4* x4 = (const float4*)d_in[0];
    const int4* dur4 = (const int4*)d_in[1];
    float* out = (float*)d_out;

    lr_fused_kernel<<<NPREP + NGATH, 256>>>(dur4, x4, (float4*)d_out, out);
}

// round 14
// speedup vs baseline: 1.1025x; 1.1025x over previous
#include <cuda_runtime.h>

// LengthRegulator: B=32, T=1024, C=384, M=4096. Durations int32; totals appended
// to out as float32 values (confirmed R4/R5).
//
// R14 = R12 structure, deeper gather MLP:
//   prep:   int4 scan, grid (8,32)=256 CTAs, 256 thr
//   gather: 16 frames/block, 256 thr, 6 independent float4 streams per thread

#define BB 32
#define TT 1024
#define CC 384
#define MM 4096
#define C4 (CC / 4)                              // 96 float4 per row
#define MAIN_ELEMS ((long long)BB * MM * CC)     // 50,331,648
#define SEG 8                                    // prep blocks per batch
#define FSEG (MM / SEG)                          // 512 frames per prep block
#define FPB 16                                   // frames per gather block
#define GT 256                                   // gather threads per block
#define EPB (FPB * C4)                           // 1536 float4 per gather block

__device__ int g_tok[BB * MM];     // token index per frame, -1 => zero-fill

// ---------------------------------------------------------------------------
// Prep: grid (SEG, BB) = 256 CTAs, 256 threads. int4 scan (4 durations/thread),
// then each thread resolves 2 frames of its segment.
// ---------------------------------------------------------------------------
__global__ __launch_bounds__(256) void lr_prep_kernel(
        const int4* __restrict__ dur4,
        float* __restrict__ out_base) {
    __shared__ int cs[TT];
    __shared__ int wsum[8];

    const int b   = blockIdx.y;
    const int seg = blockIdx.x;
    const int tid = threadIdx.x;                 // 0..255
    const int lane = tid & 31;
    const int w    = tid >> 5;                   // warp 0..7

    const int4 d = dur4[b * (TT / 4) + tid];     // 4 durations per thread
    int e = d.x + d.y + d.z + d.w;
    #pragma unroll
    for (int off = 1; off < 32; off <<= 1) {
        int n = __shfl_up_sync(0xffffffffu, e, off);
        if (lane >= off) e += n;
    }
    if (lane == 31) wsum[w] = e;
    __syncthreads();
    if (tid < 32) {
        int s = (tid < 8) ? wsum[tid] : 0;
        #pragma unroll
        for (int off = 1; off < 8; off <<= 1) {
            int n = __shfl_up_sync(0xffffffffu, s, off);
            if (lane >= off) s += n;
        }
        if (tid < 8) wsum[tid] = s;
    }
    __syncthreads();
    const int base = (w > 0) ? wsum[w - 1] : 0;
    const int end = base + e;                    // inclusive through 4t+3
    cs[4 * tid + 3] = end;
    cs[4 * tid + 2] = end - d.w;
    cs[4 * tid + 1] = end - d.w - d.z;
    cs[4 * tid + 0] = end - d.w - d.z - d.y;
    __syncthreads();

    const int total = cs[TT - 1];
    if (seg == 0 && tid == 0)
        out_base[MAIN_ELEMS + b] = (float)total; // total as float32 value

    #pragma unroll
    for (int k = 0; k < 2; ++k) {
        const int f = seg * FSEG + k * 256 + tid;
        int pos = 0;                              // upper_bound, bit construction
        #pragma unroll
        for (int step = TT / 2; step > 0; step >>= 1) {
            int cand = pos + step;               // cand-1 <= 1022
            if (cs[cand - 1] <= f) pos = cand;
        }
        g_tok[b * MM + f] = (f < total) ? pos : -1;
    }
}

// ---------------------------------------------------------------------------
// Gather: grid (MM/FPB, BB) = (256, 32) = 8192 CTAs, 256 threads.
// 16 frames/block; toks in smem; 6 independent float4 streams per thread.
// ---------------------------------------------------------------------------
__global__ __launch_bounds__(GT) void lr_gather_kernel(
        const float4* __restrict__ x4,
        float4* __restrict__ out4) {
    __shared__ int stok[FPB];
    const int b  = blockIdx.y;
    const int f0 = blockIdx.x * FPB;
    const int tid = threadIdx.x;

    if (tid < FPB)
        stok[tid] = g_tok[b * MM + f0 + tid];
    __syncthreads();

    const int obase = (b * MM + f0) * C4;        // < 12.6M, fits int
    const int xbase = b * TT * C4;

    float4 val[6];
    #pragma unroll
    for (int k = 0; k < 6; ++k) {
        const int e  = k * GT + tid;             // 0..1535
        const int fl = e / C4;                   // local frame 0..15
        const int c  = e - fl * C4;
        const int tok = stok[fl];
        val[k] = make_float4(0.f, 0.f, 0.f, 0.f);
        if (tok >= 0)
            val[k] = __ldg(&x4[xbase + tok * C4 + c]);
    }
    #pragma unroll
    for (int k = 0; k < 6; ++k)
        __stcs(&out4[obase + k * GT + tid], val[k]);
}

// ---------------------------------------------------------------------------

extern "C" void kernel_launch(void* const* d_in, const int* in_sizes, int n_in,
                              void* d_out, int out_size) {
    const float4* x4 = (const float4*)d_in[0];
    const int4* dur4 = (const int4*)d_in[1];
    float* out = (float*)d_out;

    dim3 gprep(SEG, BB);                         // (8, 32) = 256 CTAs
    lr_prep_kernel<<<gprep, 256>>>(dur4, out);

    dim3 gg(MM / FPB, BB);                       // (256, 32) = 8192 CTAs
    lr_gather_kernel<<<gg, GT>>>(x4, (float4*)d_out);
}